// round 5
// baseline (speedup 1.0000x reference)
#include <cuda_runtime.h>
#include <math.h>

// YOLO loss reduction, fused single launch, mask-predicated traffic.
// n cells: pred 30 f32/cell, tbox 4, tcls 20, mask 1 elem (dtype detected).
// Outputs 5 f32: total, reg, containing, noobj, cls.

#define S_GRID_INV (1.0f / 14.0f)
#define L_COORD 5.0f
#define L_NOOBJ 0.5f
#define TPB 256
#define PSTRIDE 31               // padded pred row in smem (gcd(31,32)=1)

__device__ double g_acc[4];      // cls, noobj(raw), reg(raw), containing
__device__ unsigned g_counter;   // zero-init; reset by last block each run

__global__ void __launch_bounds__(TPB, 6) yolo_fused_kernel(
    const float* __restrict__ pred,
    const float* __restrict__ tbox,
    const float* __restrict__ tcls,
    const void* __restrict__ maskv,
    int ncell, int n_batch, float* __restrict__ out)
{
    __shared__ float sp[TPB * PSTRIDE];    // padded pred tile (~31.7 KB)
    __shared__ unsigned char smask[TPB];
    __shared__ int s_gt1, s_bad;
    __shared__ bool s_last;
    __shared__ float sm[4][8];

    const int tid = threadIdx.x;
    const int block0 = blockIdx.x * TPB;

    if (tid == 0) { s_gt1 = 0; s_bad = 0; }
    __syncthreads();

    // ---- mask dtype detection on first 256 words (deterministic) ----
    {
        unsigned w = ((const unsigned*)maskv)[tid];
        bool gt1 = w > 1u;
        bool bad = ((w & 0xFFu) > 1u) | (((w >> 8) & 0xFFu) > 1u) |
                   (((w >> 16) & 0xFFu) > 1u) | ((w >> 24) > 1u);
        unsigned bg = __ballot_sync(0xFFFFFFFFu, gt1);
        unsigned bb = __ballot_sync(0xFFFFFFFFu, bad);
        if ((tid & 31) == 0) {
            if (bg) atomicOr(&s_gt1, 1);
            if (bb) atomicOr(&s_bad, 1);
        }
    }
    __syncthreads();
    const int mode = (s_gt1 == 0) ? 0 : (s_bad ? 2 : 1);

    // ---- mask tile ----
    const int c = block0 + tid;
    bool m = false;
    if (c < ncell) {
        if (mode == 0)      m = ((const int*)maskv)[c] != 0;
        else if (mode == 1) m = ((const unsigned char*)maskv)[c] != 0;
        else                m = ((const float*)maskv)[c] != 0.0f;
    }
    smask[tid] = m ? 1 : 0;
    __syncthreads();

    // ---- predicated, coalesced pred staging into padded smem ----
    // tile = TPB*30 floats = TPB*30/4 float4 (exact: 1920 for TPB=256)
    const bool fulltile = (block0 + TPB) <= ncell;
    if (fulltile) {
        const float4* gp4 = (const float4*)pred + (size_t)block0 * 30 / 4;
#pragma unroll
        for (int k = 0; k < 8; k++) {
            int i = tid + k * TPB;
            if (i < (TPB * 30 / 4)) {
                int f  = i * 4;          // float offset in tile [0, 7680)
                int c1 = f / 30;
                int pos = f - c1 * 30;
                int c2 = (f + 3) / 30;
                bool need = smask[c1] || (c2 != c1 && smask[c2]) ||
                            (pos <= 4 && pos + 3 >= 4) ||
                            (pos <= 9 && pos + 3 >= 9);
                if (need) {
                    float4 v = __ldcs(gp4 + i);
                    float vs0 = v.x, vs1 = v.y, vs2 = v.z, vs3 = v.w;
                    int cc = c1, pp = pos;
                    sp[cc * PSTRIDE + pp] = vs0;
                    if (++pp == 30) { pp = 0; cc++; }
                    sp[cc * PSTRIDE + pp] = vs1;
                    if (++pp == 30) { pp = 0; cc++; }
                    sp[cc * PSTRIDE + pp] = vs2;
                    if (++pp == 30) { pp = 0; cc++; }
                    sp[cc * PSTRIDE + pp] = vs3;
                }
            }
        }
    } else {
        // rare/never path: scalar staging with global bounds
        long long lim = (long long)ncell * 30 - (long long)block0 * 30;
        const float* gp = pred + (size_t)block0 * 30;
        for (int f = tid; f < TPB * 30; f += TPB) {
            if (f < lim) {
                int cc = f / 30;
                sp[cc * PSTRIDE + (f - cc * 30)] = gp[f];
            }
        }
    }
    __syncthreads();

    float s_cls = 0.f, s_noobj = 0.f, s_reg = 0.f, s_cont = 0.f;

    if (c < ncell) {
        const float* mp = sp + tid * PSTRIDE;
        if (!m) {
            float c0 = mp[4];
            float c1 = mp[9];
            s_noobj = c0 * c0 + c1 * c1;
        } else {
            // box region (10 floats), conflict-free LDS
            float pv[10];
#pragma unroll
            for (int q = 0; q < 10; q++) pv[q] = mp[q];

            // ---- class loss: stream tcls direct (predicated by mask) ----
            {
                const float4* tc4 = (const float4*)(tcls + (size_t)c * 20);
                float cls = 0.f;
#pragma unroll
                for (int j = 0; j < 5; j++) {
                    float4 t = __ldcs(tc4 + j);
                    float d0 = t.x - mp[10 + 4 * j + 0];
                    float d1 = t.y - mp[10 + 4 * j + 1];
                    float d2 = t.z - mp[10 + 4 * j + 2];
                    float d3 = t.w - mp[10 + 4 * j + 3];
                    cls += d0 * d0 + d1 * d1 + d2 * d2 + d3 * d3;
                }
                s_cls = cls;
            }

            // ---- IoU of the two pred boxes vs target ----
            float4 tb = __ldcs(((const float4*)tbox) + c);
            float t_cx = tb.x * S_GRID_INV;
            float t_cy = tb.y * S_GRID_INV;
            float t_x1 = t_cx - 0.5f * tb.z;
            float t_y1 = t_cy - 0.5f * tb.w;
            float t_x2 = t_cx + 0.5f * tb.z;
            float t_y2 = t_cy + 0.5f * tb.w;
            float area_t = (t_x2 - t_x1) * (t_y2 - t_y1);

            float iou[2];
#pragma unroll
            for (int b = 0; b < 2; b++) {
                float px = pv[5 * b + 0] * S_GRID_INV;
                float py = pv[5 * b + 1] * S_GRID_INV;
                float pw = pv[5 * b + 2];
                float ph = pv[5 * b + 3];
                float p_x1 = px - 0.5f * pw;
                float p_y1 = py - 0.5f * ph;
                float p_x2 = px + 0.5f * pw;
                float p_y2 = py + 0.5f * ph;
                float lt_x = fmaxf(t_x1, p_x1);
                float lt_y = fmaxf(t_y1, p_y1);
                float rb_x = fminf(t_x2, p_x2);
                float rb_y = fminf(t_y2, p_y2);
                float w = fmaxf(rb_x - lt_x, 0.0f);
                float h = fmaxf(rb_y - lt_y, 0.0f);
                float inter = w * h;
                float area_p = (p_x2 - p_x1) * (p_y2 - p_y1);
                iou[b] = inter / (area_t + area_p - inter);
            }

            // argmax (first max wins on tie)
            bool sel = iou[1] > iou[0];
            float best_iou = sel ? iou[1] : iou[0];
            float bb_x = sel ? pv[5] : pv[0];
            float bb_y = sel ? pv[6] : pv[1];
            float bb_w = sel ? pv[7] : pv[2];
            float bb_h = sel ? pv[8] : pv[3];
            float bb_c = sel ? pv[9] : pv[4];

            float dx = bb_x - tb.x;
            float dy = bb_y - tb.y;
            float sw = sqrtf(bb_w) - sqrtf(tb.z);
            float sh = sqrtf(bb_h) - sqrtf(tb.w);
            s_reg = dx * dx + dy * dy + sw * sw + sh * sh;

            float dc = best_iou - bb_c;
            s_cont = dc * dc;
        }
    }

    // ---- block reduction ----
#pragma unroll
    for (int off = 16; off; off >>= 1) {
        s_cls   += __shfl_down_sync(0xFFFFFFFFu, s_cls,   off);
        s_noobj += __shfl_down_sync(0xFFFFFFFFu, s_noobj, off);
        s_reg   += __shfl_down_sync(0xFFFFFFFFu, s_reg,   off);
        s_cont  += __shfl_down_sync(0xFFFFFFFFu, s_cont,  off);
    }

    int wid = tid >> 5;
    int lid = tid & 31;
    if (lid == 0) {
        sm[0][wid] = s_cls;
        sm[1][wid] = s_noobj;
        sm[2][wid] = s_reg;
        sm[3][wid] = s_cont;
    }
    __syncthreads();

    if (tid == 0) {
        float a0 = 0.f, a1 = 0.f, a2 = 0.f, a3 = 0.f;
#pragma unroll
        for (int w = 0; w < 8; w++) {
            a0 += sm[0][w];
            a1 += sm[1][w];
            a2 += sm[2][w];
            a3 += sm[3][w];
        }
        atomicAdd(&g_acc[0], (double)a0);
        atomicAdd(&g_acc[1], (double)a1);
        atomicAdd(&g_acc[2], (double)a2);
        atomicAdd(&g_acc[3], (double)a3);

        __threadfence();
        unsigned old = atomicAdd(&g_counter, 1u);
        s_last = (old == gridDim.x - 1);
    }
    __syncthreads();

    // ---- last block: finalize + reset persistent state ----
    if (s_last && tid == 0) {
        double cls   = atomicAdd(&g_acc[0], 0.0);
        double noobj = (double)L_NOOBJ * atomicAdd(&g_acc[1], 0.0);
        double reg   = (double)L_COORD * atomicAdd(&g_acc[2], 0.0);
        double cont  = atomicAdd(&g_acc[3], 0.0);
        double total = (cls + noobj + reg + cont) / (double)n_batch;
        out[0] = (float)total;
        out[1] = (float)reg;
        out[2] = (float)cont;
        out[3] = (float)noobj;
        out[4] = (float)cls;
        g_acc[0] = 0.0; g_acc[1] = 0.0; g_acc[2] = 0.0; g_acc[3] = 0.0;
        __threadfence();
        g_counter = 0u;
    }
}

extern "C" void kernel_launch(void* const* d_in, const int* in_sizes, int n_in,
                              void* d_out, int out_size) {
    // Identify inputs by element count: pred = 30n, tcls = 20n, tbox = 4n, mask = n
    const void* ptrs[4] = {d_in[0], d_in[1], d_in[2], d_in[3]};
    long long sz[4] = {in_sizes[0], in_sizes[1], in_sizes[2], in_sizes[3]};

    int im = 0;
    for (int i = 1; i < 4; i++) if (sz[i] < sz[im]) im = i;
    long long n = sz[im];

    const float* pred = nullptr;
    const float* tbox = nullptr;
    const float* tcls = nullptr;
    const void*  hmask = ptrs[im];
    for (int i = 0; i < 4; i++) {
        if (i == im) continue;
        if (sz[i] == 30 * n) pred = (const float*)ptrs[i];
        else if (sz[i] == 20 * n) tcls = (const float*)ptrs[i];
        else if (sz[i] == 4 * n) tbox = (const float*)ptrs[i];
    }

    int ncell = (int)n;                 // 802816
    int n_batch = ncell / (14 * 14);    // 4096

    int blocks = (ncell + TPB - 1) / TPB;  // 3136
    yolo_fused_kernel<<<blocks, TPB>>>(pred, tbox, tcls, hmask,
                                       ncell, n_batch, (float*)d_out);
}

// round 6
// speedup vs baseline: 1.1875x; 1.1875x over previous
#include <cuda_runtime.h>
#include <math.h>

// YOLO loss reduction, fused single launch, warp-autonomous staging.
// n cells: pred 30 f32/cell, tbox 4, tcls 20, mask 1 elem (dtype detected).
// Outputs 5 f32: total, reg, containing, noobj, cls.

#define S_GRID_INV (1.0f / 14.0f)
#define L_COORD 5.0f
#define L_NOOBJ 0.5f
#define TPB 256
#define NWARP (TPB / 32)
#define PSTRIDE 31   // padded pred row (gcd(31,32)=1 -> conflict-free LDS)
#define TSTRIDE 21   // padded tcls row

__device__ double g_acc[4];      // cls, noobj(raw), reg(raw), containing
__device__ unsigned g_counter;   // zero-init; reset by last block each run

__global__ void __launch_bounds__(TPB, 4) yolo_fused_kernel(
    const float* __restrict__ pred,
    const float* __restrict__ tbox,
    const float* __restrict__ tcls,
    const void* __restrict__ maskv,
    int ncell, int n_batch, float* __restrict__ out)
{
    __shared__ float sp[NWARP * 32 * PSTRIDE];   // 31.7 KB
    __shared__ float st[NWARP * 32 * TSTRIDE];   // 21.5 KB
    __shared__ float sm[4][NWARP];
    __shared__ bool s_last;

    const int tid  = threadIdx.x;
    const int warp = tid >> 5;
    const int lane = tid & 31;
    const int block0 = blockIdx.x * TPB;
    const int cellBase = block0 + warp * 32;
    const int c = cellBase + lane;

    float* wsp = sp + warp * (32 * PSTRIDE);
    float* wst = st + warp * (32 * TSTRIDE);

    // ---- mask dtype detection: warp-local ballot over first 32 words ----
    int mode;
    {
        unsigned w0 = ((const unsigned*)maskv)[lane];
        bool gt1 = w0 > 1u;
        bool bad = ((w0 & 0xFFu) > 1u) | (((w0 >> 8) & 0xFFu) > 1u) |
                   (((w0 >> 16) & 0xFFu) > 1u) | ((w0 >> 24) > 1u);
        unsigned bg = __ballot_sync(0xFFFFFFFFu, gt1);
        unsigned bb = __ballot_sync(0xFFFFFFFFu, bad);
        mode = (bg == 0) ? 0 : (bb ? 2 : 1);
    }

    // ---- my cell's mask ----
    bool m = false;
    if (c < ncell) {
        if (mode == 0)      m = ((const int*)maskv)[c] != 0;
        else if (mode == 1) m = ((const unsigned char*)maskv)[c] != 0;
        else                m = ((const float*)maskv)[c] != 0.0f;
    }
    const unsigned wm = __ballot_sync(0xFFFFFFFFu, m);

    // ---- warp-autonomous staging (no block barrier) ----
    if (cellBase + 32 <= ncell) {
        // pred: 960 floats = 480 float2, coalesced per warp
        const float2* gp2 = (const float2*)pred + (size_t)cellBase * 15;
#pragma unroll
        for (int k = 0; k < 15; k++) {
            int i = lane + 32 * k;
            int f = 2 * i;                 // even, so pp <= 28
            int cc = f / 30;
            int pp = f - cc * 30;
            float2 v = __ldcs(gp2 + i);
            wsp[cc * PSTRIDE + pp]     = v.x;
            wsp[cc * PSTRIDE + pp + 1] = v.y;
        }
        // tcls: 640 floats = 160 float4, 16B always within one cell
        const float4* gt4 = (const float4*)tcls + (size_t)cellBase * 5;
#pragma unroll
        for (int k = 0; k < 5; k++) {
            int i = lane + 32 * k;
            int f = 4 * i;
            int cc = f / 20;
            int pp = f - cc * 20;
            if ((wm >> cc) & 1u) {
                float4 t = __ldcs(gt4 + i);
                float* d = wst + cc * TSTRIDE + pp;
                d[0] = t.x; d[1] = t.y; d[2] = t.z; d[3] = t.w;
            }
        }
    } else {
        // tail fallback: per-lane direct copies (correct, rarely taken)
        if (c < ncell) {
            const float* gp = pred + (size_t)c * 30;
            float* d = wsp + lane * PSTRIDE;
            for (int q = 0; q < 30; q++) d[q] = gp[q];
            if (m) {
                const float* gt = tcls + (size_t)c * 20;
                float* dt = wst + lane * TSTRIDE;
                for (int q = 0; q < 20; q++) dt[q] = gt[q];
            }
        }
    }
    __syncwarp();

    float s_cls = 0.f, s_noobj = 0.f, s_reg = 0.f, s_cont = 0.f;

    if (c < ncell) {
        const float* mp = wsp + lane * PSTRIDE;
        if (!m) {
            float c0 = mp[4];
            float c1 = mp[9];
            s_noobj = c0 * c0 + c1 * c1;
        } else {
            float pv[10];
#pragma unroll
            for (int q = 0; q < 10; q++) pv[q] = mp[q];

            // ---- class loss ----
            {
                const float* mt = wst + lane * TSTRIDE;
                float cls = 0.f;
#pragma unroll
                for (int j = 0; j < 20; j++) {
                    float d = mt[j] - mp[10 + j];
                    cls += d * d;
                }
                s_cls = cls;
            }

            // ---- IoU of the two pred boxes vs target ----
            float4 tb = __ldcs(((const float4*)tbox) + c);
            float t_cx = tb.x * S_GRID_INV;
            float t_cy = tb.y * S_GRID_INV;
            float t_x1 = t_cx - 0.5f * tb.z;
            float t_y1 = t_cy - 0.5f * tb.w;
            float t_x2 = t_cx + 0.5f * tb.z;
            float t_y2 = t_cy + 0.5f * tb.w;
            float area_t = (t_x2 - t_x1) * (t_y2 - t_y1);

            float iou[2];
#pragma unroll
            for (int b = 0; b < 2; b++) {
                float px = pv[5 * b + 0] * S_GRID_INV;
                float py = pv[5 * b + 1] * S_GRID_INV;
                float pw = pv[5 * b + 2];
                float ph = pv[5 * b + 3];
                float p_x1 = px - 0.5f * pw;
                float p_y1 = py - 0.5f * ph;
                float p_x2 = px + 0.5f * pw;
                float p_y2 = py + 0.5f * ph;
                float lt_x = fmaxf(t_x1, p_x1);
                float lt_y = fmaxf(t_y1, p_y1);
                float rb_x = fminf(t_x2, p_x2);
                float rb_y = fminf(t_y2, p_y2);
                float w = fmaxf(rb_x - lt_x, 0.0f);
                float h = fmaxf(rb_y - lt_y, 0.0f);
                float inter = w * h;
                float area_p = (p_x2 - p_x1) * (p_y2 - p_y1);
                iou[b] = inter / (area_t + area_p - inter);
            }

            // argmax (first max wins on tie)
            bool sel = iou[1] > iou[0];
            float best_iou = sel ? iou[1] : iou[0];
            float bb_x = sel ? pv[5] : pv[0];
            float bb_y = sel ? pv[6] : pv[1];
            float bb_w = sel ? pv[7] : pv[2];
            float bb_h = sel ? pv[8] : pv[3];
            float bb_c = sel ? pv[9] : pv[4];

            float dx = bb_x - tb.x;
            float dy = bb_y - tb.y;
            float sw = sqrtf(bb_w) - sqrtf(tb.z);
            float sh = sqrtf(bb_h) - sqrtf(tb.w);
            s_reg = dx * dx + dy * dy + sw * sw + sh * sh;

            float dc = best_iou - bb_c;
            s_cont = dc * dc;
        }
    }

    // ---- warp reduction, then block reduction (single barrier) ----
#pragma unroll
    for (int off = 16; off; off >>= 1) {
        s_cls   += __shfl_down_sync(0xFFFFFFFFu, s_cls,   off);
        s_noobj += __shfl_down_sync(0xFFFFFFFFu, s_noobj, off);
        s_reg   += __shfl_down_sync(0xFFFFFFFFu, s_reg,   off);
        s_cont  += __shfl_down_sync(0xFFFFFFFFu, s_cont,  off);
    }
    if (lane == 0) {
        sm[0][warp] = s_cls;
        sm[1][warp] = s_noobj;
        sm[2][warp] = s_reg;
        sm[3][warp] = s_cont;
    }
    __syncthreads();

    if (tid == 0) {
        float a0 = 0.f, a1 = 0.f, a2 = 0.f, a3 = 0.f;
#pragma unroll
        for (int w = 0; w < NWARP; w++) {
            a0 += sm[0][w];
            a1 += sm[1][w];
            a2 += sm[2][w];
            a3 += sm[3][w];
        }
        atomicAdd(&g_acc[0], (double)a0);
        atomicAdd(&g_acc[1], (double)a1);
        atomicAdd(&g_acc[2], (double)a2);
        atomicAdd(&g_acc[3], (double)a3);

        __threadfence();
        unsigned old = atomicAdd(&g_counter, 1u);
        s_last = (old == gridDim.x - 1);
    }
    __syncthreads();

    // ---- last block: finalize + reset persistent state ----
    if (s_last && tid == 0) {
        double cls   = atomicAdd(&g_acc[0], 0.0);
        double noobj = (double)L_NOOBJ * atomicAdd(&g_acc[1], 0.0);
        double reg   = (double)L_COORD * atomicAdd(&g_acc[2], 0.0);
        double cont  = atomicAdd(&g_acc[3], 0.0);
        double total = (cls + noobj + reg + cont) / (double)n_batch;
        out[0] = (float)total;
        out[1] = (float)reg;
        out[2] = (float)cont;
        out[3] = (float)noobj;
        out[4] = (float)cls;
        g_acc[0] = 0.0; g_acc[1] = 0.0; g_acc[2] = 0.0; g_acc[3] = 0.0;
        __threadfence();
        g_counter = 0u;
    }
}

extern "C" void kernel_launch(void* const* d_in, const int* in_sizes, int n_in,
                              void* d_out, int out_size) {
    // Identify inputs by element count: pred = 30n, tcls = 20n, tbox = 4n, mask = n
    const void* ptrs[4] = {d_in[0], d_in[1], d_in[2], d_in[3]};
    long long sz[4] = {in_sizes[0], in_sizes[1], in_sizes[2], in_sizes[3]};

    int im = 0;
    for (int i = 1; i < 4; i++) if (sz[i] < sz[im]) im = i;
    long long n = sz[im];

    const float* pred = nullptr;
    const float* tbox = nullptr;
    const float* tcls = nullptr;
    const void*  hmask = ptrs[im];
    for (int i = 0; i < 4; i++) {
        if (i == im) continue;
        if (sz[i] == 30 * n) pred = (const float*)ptrs[i];
        else if (sz[i] == 20 * n) tcls = (const float*)ptrs[i];
        else if (sz[i] == 4 * n) tbox = (const float*)ptrs[i];
    }

    int ncell = (int)n;                 // 802816
    int n_batch = ncell / (14 * 14);    // 4096

    int blocks = (ncell + TPB - 1) / TPB;  // 3136
    yolo_fused_kernel<<<blocks, TPB>>>(pred, tbox, tcls, hmask,
                                       ncell, n_batch, (float*)d_out);
}

// round 7
// speedup vs baseline: 1.3940x; 1.1739x over previous
#include <cuda_runtime.h>
#include <math.h>

// YOLO loss reduction — fused single launch, warp-autonomous 64-cell tiles,
// LDG.128 staging, tcls streamed direct. Outputs 5 f32.

#define S_GRID_INV (1.0f / 14.0f)
#define L_COORD 5.0f
#define L_NOOBJ 0.5f
#define TPB 256
#define NWARP (TPB / 32)
#define CPW 64                 // cells per warp
#define CPB (NWARP * CPW)      // 512 cells per block
#define PROW 30                // floats per pred row (unpadded)

__device__ double g_acc[4];      // cls, noobj(raw), reg(raw), containing
__device__ unsigned g_counter;   // zero-init; reset by last block each run

__global__ void __launch_bounds__(TPB, 3) yolo_fused_kernel(
    const float* __restrict__ pred,
    const float* __restrict__ tbox,
    const float* __restrict__ tcls,
    const void* __restrict__ maskv,
    int ncell, int n_batch, float* __restrict__ out)
{
    __shared__ float sp[NWARP * CPW * PROW];   // 60 KB
    __shared__ float sm[4][NWARP];
    __shared__ bool s_last;

    const int tid  = threadIdx.x;
    const int warp = tid >> 5;
    const int lane = tid & 31;
    const int cellBase = blockIdx.x * CPB + warp * CPW;

    float* wsp = sp + warp * (CPW * PROW);

    // ---- mask dtype detection: warp-local ballot over first 32 words ----
    int mode;
    {
        unsigned w0 = ((const unsigned*)maskv)[lane];
        bool gt1 = w0 > 1u;
        bool bad = ((w0 & 0xFFu) > 1u) | (((w0 >> 8) & 0xFFu) > 1u) |
                   (((w0 >> 16) & 0xFFu) > 1u) | ((w0 >> 24) > 1u);
        unsigned bg = __ballot_sync(0xFFFFFFFFu, gt1);
        unsigned bb = __ballot_sync(0xFFFFFFFFu, bad);
        mode = (bg == 0) ? 0 : (bb ? 2 : 1);
    }

    // ---- masks for my two cells ----
    const int c0 = cellBase + lane;
    const int c1 = cellBase + 32 + lane;
    bool m0 = false, m1 = false;
    if (mode == 0) {
        const int* mi = (const int*)maskv;
        if (c0 < ncell) m0 = mi[c0] != 0;
        if (c1 < ncell) m1 = mi[c1] != 0;
    } else if (mode == 1) {
        const unsigned char* mb = (const unsigned char*)maskv;
        if (c0 < ncell) m0 = mb[c0] != 0;
        if (c1 < ncell) m1 = mb[c1] != 0;
    } else {
        const float* mf = (const float*)maskv;
        if (c0 < ncell) m0 = mf[c0] != 0.0f;
        if (c1 < ncell) m1 = mf[c1] != 0.0f;
    }

    // ---- warp-autonomous pred staging: 64 cells = 1920 floats = 480 float4 ----
    if (cellBase + CPW <= ncell) {
        const float4* gp4 = (const float4*)pred + (size_t)cellBase * 30 / 4;
        float4* sp4 = (float4*)wsp;
#pragma unroll
        for (int k = 0; k < 15; k++) {
            int i = lane + 32 * k;
            sp4[i] = __ldcs(gp4 + i);
        }
    } else {
        // tail fallback (not taken for ncell multiple of 512)
        const float* gp = pred + (size_t)cellBase * 30;
        long long lim = ((long long)ncell - cellBase) * 30;
        for (int f = lane; f < CPW * PROW; f += 32)
            if (f < lim) wsp[f] = gp[f];
    }
    __syncwarp();

    float s_cls = 0.f, s_noobj = 0.f, s_reg = 0.f, s_cont = 0.f;

    // ---- process my two cells ----
#pragma unroll
    for (int half = 0; half < 2; half++) {
        const int c = half ? c1 : c0;
        const bool m = half ? m1 : m0;
        if (c >= ncell) continue;

        const int r = lane + 32 * half;
        const float2* mp2 = (const float2*)(wsp + r * PROW);  // 8B-aligned

        if (!m) {
            float cf0 = mp2[2].x;   // float idx 4
            float cf1 = mp2[4].y;   // float idx 9
            s_noobj += cf0 * cf0 + cf1 * cf1;
        } else {
            // box region: floats 0..9
            float pv[10];
#pragma unroll
            for (int j = 0; j < 5; j++) {
                float2 v = mp2[j];
                pv[2 * j]     = v.x;
                pv[2 * j + 1] = v.y;
            }

            // ---- class loss: tcls streamed direct, pred classes from smem ----
            {
                const float4* tc4 = (const float4*)tcls + (size_t)c * 5;
                const float2* mc2 = (const float2*)(wsp + r * PROW + 10);
                float cls = 0.f;
#pragma unroll
                for (int j = 0; j < 5; j++) {
                    float4 t = __ldcs(tc4 + j);
                    float2 a = mc2[2 * j];
                    float2 b = mc2[2 * j + 1];
                    float d0 = t.x - a.x;
                    float d1 = t.y - a.y;
                    float d2 = t.z - b.x;
                    float d3 = t.w - b.y;
                    cls += d0 * d0 + d1 * d1 + d2 * d2 + d3 * d3;
                }
                s_cls += cls;
            }

            // ---- IoU of the two pred boxes vs target ----
            float4 tb = __ldcs(((const float4*)tbox) + c);
            float t_cx = tb.x * S_GRID_INV;
            float t_cy = tb.y * S_GRID_INV;
            float t_x1 = t_cx - 0.5f * tb.z;
            float t_y1 = t_cy - 0.5f * tb.w;
            float t_x2 = t_cx + 0.5f * tb.z;
            float t_y2 = t_cy + 0.5f * tb.w;
            float area_t = (t_x2 - t_x1) * (t_y2 - t_y1);

            float iou[2];
#pragma unroll
            for (int b = 0; b < 2; b++) {
                float px = pv[5 * b + 0] * S_GRID_INV;
                float py = pv[5 * b + 1] * S_GRID_INV;
                float pw = pv[5 * b + 2];
                float ph = pv[5 * b + 3];
                float p_x1 = px - 0.5f * pw;
                float p_y1 = py - 0.5f * ph;
                float p_x2 = px + 0.5f * pw;
                float p_y2 = py + 0.5f * ph;
                float lt_x = fmaxf(t_x1, p_x1);
                float lt_y = fmaxf(t_y1, p_y1);
                float rb_x = fminf(t_x2, p_x2);
                float rb_y = fminf(t_y2, p_y2);
                float w = fmaxf(rb_x - lt_x, 0.0f);
                float h = fmaxf(rb_y - lt_y, 0.0f);
                float inter = w * h;
                float area_p = (p_x2 - p_x1) * (p_y2 - p_y1);
                iou[b] = inter / (area_t + area_p - inter);
            }

            // argmax (first max wins on tie)
            bool sel = iou[1] > iou[0];
            float best_iou = sel ? iou[1] : iou[0];
            float bb_x = sel ? pv[5] : pv[0];
            float bb_y = sel ? pv[6] : pv[1];
            float bb_w = sel ? pv[7] : pv[2];
            float bb_h = sel ? pv[8] : pv[3];
            float bb_c = sel ? pv[9] : pv[4];

            float dx = bb_x - tb.x;
            float dy = bb_y - tb.y;
            float sw = sqrtf(bb_w) - sqrtf(tb.z);
            float sh = sqrtf(bb_h) - sqrtf(tb.w);
            s_reg += dx * dx + dy * dy + sw * sw + sh * sh;

            float dc = best_iou - bb_c;
            s_cont += dc * dc;
        }
    }

    // ---- warp reduction, then block reduction ----
#pragma unroll
    for (int off = 16; off; off >>= 1) {
        s_cls   += __shfl_down_sync(0xFFFFFFFFu, s_cls,   off);
        s_noobj += __shfl_down_sync(0xFFFFFFFFu, s_noobj, off);
        s_reg   += __shfl_down_sync(0xFFFFFFFFu, s_reg,   off);
        s_cont  += __shfl_down_sync(0xFFFFFFFFu, s_cont,  off);
    }
    if (lane == 0) {
        sm[0][warp] = s_cls;
        sm[1][warp] = s_noobj;
        sm[2][warp] = s_reg;
        sm[3][warp] = s_cont;
    }
    __syncthreads();

    if (tid == 0) {
        float a0 = 0.f, a1 = 0.f, a2 = 0.f, a3 = 0.f;
#pragma unroll
        for (int w = 0; w < NWARP; w++) {
            a0 += sm[0][w];
            a1 += sm[1][w];
            a2 += sm[2][w];
            a3 += sm[3][w];
        }
        atomicAdd(&g_acc[0], (double)a0);
        atomicAdd(&g_acc[1], (double)a1);
        atomicAdd(&g_acc[2], (double)a2);
        atomicAdd(&g_acc[3], (double)a3);

        __threadfence();
        unsigned old = atomicAdd(&g_counter, 1u);
        s_last = (old == gridDim.x - 1);
    }
    __syncthreads();

    // ---- last block: finalize + reset persistent state ----
    if (s_last && tid == 0) {
        double cls   = atomicAdd(&g_acc[0], 0.0);
        double noobj = (double)L_NOOBJ * atomicAdd(&g_acc[1], 0.0);
        double reg   = (double)L_COORD * atomicAdd(&g_acc[2], 0.0);
        double cont  = atomicAdd(&g_acc[3], 0.0);
        double total = (cls + noobj + reg + cont) / (double)n_batch;
        out[0] = (float)total;
        out[1] = (float)reg;
        out[2] = (float)cont;
        out[3] = (float)noobj;
        out[4] = (float)cls;
        g_acc[0] = 0.0; g_acc[1] = 0.0; g_acc[2] = 0.0; g_acc[3] = 0.0;
        __threadfence();
        g_counter = 0u;
    }
}

extern "C" void kernel_launch(void* const* d_in, const int* in_sizes, int n_in,
                              void* d_out, int out_size) {
    // Identify inputs by element count: pred = 30n, tcls = 20n, tbox = 4n, mask = n
    const void* ptrs[4] = {d_in[0], d_in[1], d_in[2], d_in[3]};
    long long sz[4] = {in_sizes[0], in_sizes[1], in_sizes[2], in_sizes[3]};

    int im = 0;
    for (int i = 1; i < 4; i++) if (sz[i] < sz[im]) im = i;
    long long n = sz[im];

    const float* pred = nullptr;
    const float* tbox = nullptr;
    const float* tcls = nullptr;
    const void*  hmask = ptrs[im];
    for (int i = 0; i < 4; i++) {
        if (i == im) continue;
        if (sz[i] == 30 * n) pred = (const float*)ptrs[i];
        else if (sz[i] == 20 * n) tcls = (const float*)ptrs[i];
        else if (sz[i] == 4 * n) tbox = (const float*)ptrs[i];
    }

    int ncell = (int)n;                 // 802816
    int n_batch = ncell / (14 * 14);    // 4096

    int blocks = (ncell + CPB - 1) / CPB;  // 1568
    yolo_fused_kernel<<<blocks, TPB>>>(pred, tbox, tcls, hmask,
                                       ncell, n_batch, (float*)d_out);
}